// round 14
// baseline (speedup 1.0000x reference)
#include <cuda_runtime.h>
#include <cuda_fp16.h>
#include <math.h>
#include <stdint.h>

#define TPB 128
#define BM  64
#define BN  64
#define DHD 64
#define K2E 0.1803368801f   // log2(e)/8

#define BH_MAX 32
#define N_MAX  2048
#define MAXE   (BH_MAX * N_MAX * DHD)

// stage: 128 rows x 128B (rows 0-63 = K, 64-127 = V); 3 stages
#define STG 16384
#define SMEM_TOTAL (3 * STG)

__device__ __align__(16) __half   g_qh[MAXE];
__device__ __align__(16) __half   g_kv[2 * MAXE];            // [bh][t][128 rows][64 halves]
__device__ float    g_qn2[BH_MAX * N_MAX];
__device__ float    g_maxk2[BH_MAX];
__device__ __align__(16) uint32_t g_mask[N_MAX * N_MAX / 2]; // [row][t][qd][nb] AND-words

// ---------------- helpers ----------------
__device__ __forceinline__ uint32_t smem_u32(const void* p) {
    uint32_t a;
    asm("{ .reg .u64 t; cvta.to.shared.u64 t, %1; cvt.u32.u64 %0, t; }" : "=r"(a) : "l"(p));
    return a;
}
__device__ __forceinline__ void cp16(uint32_t dst, const void* src) {
    asm volatile("cp.async.cg.shared.global [%0], [%1], 16;" :: "r"(dst), "l"(src));
}
#define CP_COMMIT() asm volatile("cp.async.commit_group;" ::: "memory")
#define CP_WAIT0()  asm volatile("cp.async.wait_group 0;" ::: "memory")
#define CP_WAIT1()  asm volatile("cp.async.wait_group 1;" ::: "memory")

__device__ __forceinline__ void ldsm_x4(uint32_t* r, uint32_t a) {
    asm volatile("ldmatrix.sync.aligned.m8n8.x4.shared.b16 {%0,%1,%2,%3}, [%4];"
                 : "=r"(r[0]), "=r"(r[1]), "=r"(r[2]), "=r"(r[3]) : "r"(a));
}
__device__ __forceinline__ void ldsm_x4t(uint32_t* r, uint32_t a) {
    asm volatile("ldmatrix.sync.aligned.m8n8.x4.trans.shared.b16 {%0,%1,%2,%3}, [%4];"
                 : "=r"(r[0]), "=r"(r[1]), "=r"(r[2]), "=r"(r[3]) : "r"(a));
}
__device__ __forceinline__ void mma16816(float* c, const uint32_t* a, uint32_t b0, uint32_t b1) {
    asm volatile("mma.sync.aligned.m16n8k16.row.col.f32.f16.f16.f32 "
                 "{%0,%1,%2,%3}, {%4,%5,%6,%7}, {%8,%9}, {%0,%1,%2,%3};"
                 : "+f"(c[0]), "+f"(c[1]), "+f"(c[2]), "+f"(c[3])
                 : "r"(a[0]), "r"(a[1]), "r"(a[2]), "r"(a[3]), "r"(b0), "r"(b1));
}
__device__ __forceinline__ float ex2(float x) {
    float r; asm("ex2.approx.f32 %0, %1;" : "=f"(r) : "f"(x)); return r;
}
__device__ __forceinline__ uint32_t h2bits(__half2 h) { return *(uint32_t*)&h; }
__device__ __forceinline__ uint32_t swzo(int row, int colb) {
    return (uint32_t)((row * 128 + colb) ^ ((row & 7) << 4));
}

// ---------------- merged prepass (unchanged) ----------------
__global__ void prepass_kernel(const int4* __restrict__ adj,
                               const float4* __restrict__ Q,
                               const float4* __restrict__ K,
                               const float4* __restrict__ V,
                               int N, int adjB)
{
    if (blockIdx.x < adjB) {
        const int g   = blockIdx.x * 256 + threadIdx.x;
        const int row = g >> 6, seg = g & 63;
        const int t   = seg >> 1, h = seg & 1;
        const int4* bp = adj + (size_t)row * (N >> 2) + t * 16 + h * 8;
        int4 a[8];
        #pragma unroll
        for (int i = 0; i < 8; i++) a[i] = bp[i];
        uint32_t w[4][4];
        #pragma unroll
        for (int i = 0; i < 4; i++) {
            int4 lo = a[2 * i], hi = a[2 * i + 1];
            w[0][i] = (lo.x > 0 ? 0xFFFFu : 0u) | (lo.y > 0 ? 0xFFFF0000u : 0u);
            w[1][i] = (lo.z > 0 ? 0xFFFFu : 0u) | (lo.w > 0 ? 0xFFFF0000u : 0u);
            w[2][i] = (hi.x > 0 ? 0xFFFFu : 0u) | (hi.y > 0 ? 0xFFFF0000u : 0u);
            w[3][i] = (hi.z > 0 ? 0xFFFFu : 0u) | (hi.w > 0 ? 0xFFFF0000u : 0u);
        }
        const int nT = N >> 6;
        #pragma unroll
        for (int qd = 0; qd < 4; qd++)
            ((uint4*)g_mask)[(((size_t)row * nT + t) * 4 + qd) * 2 + h] =
                make_uint4(w[qd][0], w[qd][1], w[qd][2], w[qd][3]);
        return;
    }
    __shared__ float skn[16];
    const int idx = (blockIdx.x - adjB) * 256 + threadIdx.x;
    float4 q = Q[idx], k = K[idx], v = V[idx];

    ((uint2*)g_qh)[idx] = make_uint2(h2bits(__floats2half2_rn(q.x, q.y)),
                                     h2bits(__floats2half2_rn(q.z, q.w)));
    const int rl  = idx >> 4;
    const int bh  = rl / N;
    const int row = rl - bh * N;
    const int t   = row >> 6, r = row & 63, c4 = idx & 15;
    const size_t u2 = ((size_t)(bh * (N >> 6) + t) * 128 + r) * 16 + c4;
    ((uint2*)g_kv)[u2]        = make_uint2(h2bits(__floats2half2_rn(k.x, k.y)),
                                           h2bits(__floats2half2_rn(k.z, k.w)));
    ((uint2*)g_kv)[u2 + 1024] = make_uint2(h2bits(__floats2half2_rn(v.x, v.y)),
                                           h2bits(__floats2half2_rn(v.z, v.w)));

    float qn2 = q.x * q.x + q.y * q.y + q.z * q.z + q.w * q.w;
    float kn2 = k.x * k.x + k.y * k.y + k.z * k.z + k.w * k.w;
    #pragma unroll
    for (int o = 8; o; o >>= 1) {
        qn2 += __shfl_xor_sync(0xffffffffu, qn2, o);
        kn2 += __shfl_xor_sync(0xffffffffu, kn2, o);
    }
    if ((threadIdx.x & 15) == 0) {
        g_qn2[idx >> 4] = qn2;
        skn[threadIdx.x >> 4] = kn2;
    }
    __syncthreads();
    if (threadIdx.x == 0) {
        float m = skn[0];
        #pragma unroll
        for (int i = 1; i < 16; i++) m = fmaxf(m, skn[i]);
        atomicMax((int*)&g_maxk2[bh], __float_as_int(m));
    }
}

// ---------------- main kernel: 2m x 2n warp split (warp = 32 rows x 32 keys) ----------------
__global__ __launch_bounds__(TPB, 3)
void gat_hmma10_kernel(float* __restrict__ out, int N)
{
    extern __shared__ char sm[];
    const uint32_t smb = smem_u32(sm);

    const int tid  = threadIdx.x;
    const int wid  = tid >> 5;
    const int lane = tid & 31;
    const int mg   = lane >> 3;
    const int mr   = lane & 7;
    const int r4   = lane >> 2;
    const int qd   = lane & 3;

    const int wm   = wid & 1;        // m-half: rows wm*32 .. +32
    const int wn   = wid >> 1;       // n-half: keys wn*32 .. +32

    const int bh   = blockIdx.y;
    const int row0 = blockIdx.x * BM;
    const int nT   = N / BN;

    // ---- Q fragments via stage0 ----
    {
        const char* qhB = (const char*)g_qh + ((size_t)bh * N + row0) * (DHD * 2);
        #pragma unroll
        for (int i = 0; i < 4; i++) {
            int idx = tid + i * TPB;
            int row = idx >> 3, c = idx & 7;
            cp16(smb + swzo(row, c * 16), qhB + row * 128 + c * 16);
        }
        CP_COMMIT(); CP_WAIT0();
        __syncthreads();
    }
    uint32_t qh[2][4][4];
    #pragma unroll
    for (int mt = 0; mt < 2; mt++) {
        const int arow = wm * 32 + mt * 16 + ((mg & 1) << 3) + mr;
        #pragma unroll
        for (int kb = 0; kb < 4; kb++)
            ldsm_x4(qh[mt][kb], smb + swzo(arow, kb * 32 + ((mg >> 1) << 4)));
    }
    __syncthreads();

    // ---- per-row biases (4 row-groups of the warp's 32 rows) ----
    const float mk2 = g_maxk2[bh];
    const int rowb = row0 + wm * 32 + r4;
    const float sb00 = 14.0f - sqrtf(g_qn2[(size_t)bh * N + rowb]      * mk2) * K2E;
    const float sb01 = 14.0f - sqrtf(g_qn2[(size_t)bh * N + rowb +  8] * mk2) * K2E;
    const float sb10 = 14.0f - sqrtf(g_qn2[(size_t)bh * N + rowb + 16] * mk2) * K2E;
    const float sb11 = 14.0f - sqrtf(g_qn2[(size_t)bh * N + rowb + 24] * mk2) * K2E;

    // ---- mask pointer: rows (rowb + {0,8,16,24}), keys wn*32.. (nb = wn*4 + 0..3) ----
    const uint32_t* mp = g_mask + (size_t)rowb * nT * 32 + qd * 8 + wn * 4;
    const size_t rstep = (size_t)8 * nT * 32;   // +8 rows
    const uint32_t bo = (lane < 4) ? 0x3C003C00u : 0u;

    // ---- hoisted ldsm addresses ----
    const uint32_t mrx = (uint32_t)(mr << 4);
    uint32_t addrS[4], addrV[4];
    {
        uint32_t bS = smb + (uint32_t)((((mg >> 1) << 3) + mr) * 128);
        uint32_t bV = smb + 8192 + (uint32_t)((((mg & 1) << 3) + mr) * 128);
        #pragma unroll
        for (int k = 0; k < 4; k++) {
            addrS[k] = bS + ((uint32_t)(k * 32 + ((mg & 1) << 4)) ^ mrx);
            addrV[k] = bV + ((uint32_t)(k * 32 + ((mg >> 1) << 4)) ^ mrx);
        }
    }
    const uint32_t nOff = (uint32_t)(wn * 2) * 2048;   // warp's key-half offset (16-row units)

    // ---- cp.async bases ----
    const uint32_t so0 = (uint32_t)((tid >> 3) * 128 + (((tid & 7) * 16) ^ (((tid >> 3) & 7) << 4)));
    const char* kvSrc = (const char*)g_kv + (size_t)bh * N * 256 + (tid >> 3) * 128 + (tid & 7) * 16;
    uint32_t cpDst = smb + STG + so0;
    int cpStage = 1;

    float o[2][8][4];
    #pragma unroll
    for (int mt = 0; mt < 2; mt++)
        #pragma unroll
        for (int i = 0; i < 8; i++)
            #pragma unroll
            for (int j = 0; j < 4; j++) o[mt][i][j] = 0.f;
    float lf[2][4] = {{0.f, 0.f, 0.f, 0.f}, {0.f, 0.f, 0.f, 0.f}};

    // prefetch tile 0 -> stage 0
    #pragma unroll
    for (int i = 0; i < 8; i++) cp16(smb + so0 + i * 2048, kvSrc + i * 2048);
    CP_COMMIT();
    kvSrc += 16384;

    int st = 0;
    for (int t = 0; t < nT; t++) {
        if (t + 1 < nT) {
            #pragma unroll
            for (int i = 0; i < 8; i++) cp16(cpDst + i * 2048, kvSrc + i * 2048);
            CP_COMMIT(); CP_WAIT1();
            kvSrc += 16384;
            int d2 = (cpStage == 2) ? -2 * STG : STG;
            cpStage = (cpStage == 2) ? 0 : cpStage + 1;
            cpDst += d2;
        } else {
            CP_WAIT0();
        }
        __syncthreads();   // single barrier per tile (3-stage ring)

        // hoisted mask loads: 4 row-groups x 4 local n8-words
        const uint4 q0 = *(const uint4*)(mp);
        const uint4 q1 = *(const uint4*)(mp + rstep);
        const uint4 q2 = *(const uint4*)(mp + 2 * rstep);
        const uint4 q3 = *(const uint4*)(mp + 3 * rstep);
        mp += 32;
        const uint32_t mw00[4] = {q0.x, q0.y, q0.z, q0.w};  // mt0 rows r4
        const uint32_t mw01[4] = {q1.x, q1.y, q1.z, q1.w};  // mt0 rows r4+8
        const uint32_t mw10[4] = {q2.x, q2.y, q2.z, q2.w};  // mt1 rows r4
        const uint32_t mw11[4] = {q3.x, q3.y, q3.z, q3.w};  // mt1 rows r4+8

        // ---- two n16 sub-steps over the warp's 32 keys ----
        #pragma unroll
        for (int j = 0; j < 2; j++) {
            // S for n16-group (wn*2 + j), both m-tiles share each K fragment
            float c[16];
            #pragma unroll
            for (int i = 0; i < 16; i++) c[i] = 0.f;
            #pragma unroll
            for (int kb = 0; kb < 4; kb++) {
                uint32_t bhr[4];
                ldsm_x4(bhr, addrS[kb] + nOff + j * 2048);
                mma16816(c,      qh[0][kb], bhr[0], bhr[1]);
                mma16816(c + 4,  qh[0][kb], bhr[2], bhr[3]);
                mma16816(c + 8,  qh[1][kb], bhr[0], bhr[1]);
                mma16816(c + 12, qh[1][kb], bhr[2], bhr[3]);
            }

            // exp
            c[0]  = ex2(fmaf(c[0],  K2E, sb00));
            c[1]  = ex2(fmaf(c[1],  K2E, sb00));
            c[2]  = ex2(fmaf(c[2],  K2E, sb01));
            c[3]  = ex2(fmaf(c[3],  K2E, sb01));
            c[4]  = ex2(fmaf(c[4],  K2E, sb00));
            c[5]  = ex2(fmaf(c[5],  K2E, sb00));
            c[6]  = ex2(fmaf(c[6],  K2E, sb01));
            c[7]  = ex2(fmaf(c[7],  K2E, sb01));
            c[8]  = ex2(fmaf(c[8],  K2E, sb10));
            c[9]  = ex2(fmaf(c[9],  K2E, sb10));
            c[10] = ex2(fmaf(c[10], K2E, sb11));
            c[11] = ex2(fmaf(c[11], K2E, sb11));
            c[12] = ex2(fmaf(c[12], K2E, sb10));
            c[13] = ex2(fmaf(c[13], K2E, sb10));
            c[14] = ex2(fmaf(c[14], K2E, sb11));
            c[15] = ex2(fmaf(c[15], K2E, sb11));

            // P fragments (k16 = this n16 key group), masked
            uint32_t ph0[4], ph1[4];
            ph0[0] = h2bits(__floats2half2_rn(c[0],  c[1]))  & mw00[2 * j];
            ph0[1] = h2bits(__floats2half2_rn(c[2],  c[3]))  & mw01[2 * j];
            ph0[2] = h2bits(__floats2half2_rn(c[4],  c[5]))  & mw00[2 * j + 1];
            ph0[3] = h2bits(__floats2half2_rn(c[6],  c[7]))  & mw01[2 * j + 1];
            ph1[0] = h2bits(__floats2half2_rn(c[8],  c[9]))  & mw10[2 * j];
            ph1[1] = h2bits(__floats2half2_rn(c[10], c[11])) & mw11[2 * j];
            ph1[2] = h2bits(__floats2half2_rn(c[12], c[13])) & mw10[2 * j + 1];
            ph1[3] = h2bits(__floats2half2_rn(c[14], c[15])) & mw11[2 * j + 1];

            // PV: both m-tiles share each V fragment
            #pragma unroll
            for (int jd = 0; jd < 4; jd++) {
                uint32_t vh4[4];
                ldsm_x4t(vh4, addrV[jd] + nOff + j * 2048);
                mma16816(o[0][2 * jd],     ph0, vh4[0], vh4[1]);
                mma16816(o[0][2 * jd + 1], ph0, vh4[2], vh4[3]);
                mma16816(o[1][2 * jd],     ph1, vh4[0], vh4[1]);
                mma16816(o[1][2 * jd + 1], ph1, vh4[2], vh4[3]);
            }
            mma16816(lf[0], ph0, bo, bo);
            mma16816(lf[1], ph1, bo, bo);
        }

        // rotate stage bases
        int d = (st == 2) ? -2 * STG : STG;
        st = (st == 2) ? 0 : st + 1;
        #pragma unroll
        for (int k = 0; k < 4; k++) { addrS[k] += d; addrV[k] += d; }
    }

    // ---- cross-warp combine (wn=1 partials -> smem; wn=0 adds, normalizes, stores) ----
    const float l00 = __shfl_sync(0xffffffffu, lf[0][0], lane & 28);
    const float l01 = __shfl_sync(0xffffffffu, lf[0][2], lane & 28);
    const float l10 = __shfl_sync(0xffffffffu, lf[1][0], lane & 28);
    const float l11 = __shfl_sync(0xffffffffu, lf[1][2], lane & 28);

    __syncthreads();   // all tile reads complete before smem reuse
    float* sO = (float*)sm;            // [64 rows][stride 66]
    float* sL = (float*)(sm + 64 * 66 * 4);

    if (wn == 1) {
        #pragma unroll
        for (int mt = 0; mt < 2; mt++) {
            const int ra = wm * 32 + mt * 16 + r4;
            #pragma unroll
            for (int nb = 0; nb < 8; nb++) {
                const int col = nb * 8 + qd * 2;
                *(float2*)&sO[ra * 66 + col]       = make_float2(o[mt][nb][0], o[mt][nb][1]);
                *(float2*)&sO[(ra + 8) * 66 + col] = make_float2(o[mt][nb][2], o[mt][nb][3]);
            }
        }
        if (qd == 0) {
            sL[wm * 32 + r4]      = l00;
            sL[wm * 32 + 8 + r4]  = l01;
            sL[wm * 32 + 16 + r4] = l10;
            sL[wm * 32 + 24 + r4] = l11;
        }
    }
    __syncthreads();

    if (wn == 0) {
        const float i00 = 1.0f / (l00 + sL[wm * 32 + r4]);
        const float i01 = 1.0f / (l01 + sL[wm * 32 + 8 + r4]);
        const float i10 = 1.0f / (l10 + sL[wm * 32 + 16 + r4]);
        const float i11 = 1.0f / (l11 + sL[wm * 32 + 24 + r4]);
        float2* op = (float2*)out;
        #pragma unroll
        for (int mt = 0; mt < 2; mt++) {
            const int ra = wm * 32 + mt * 16 + r4;
            const int orow = row0 + ra;
            const float iA = mt ? i10 : i00;
            const float iB = mt ? i11 : i01;
            #pragma unroll
            for (int nb = 0; nb < 8; nb++) {
                const int dcol = nb * 8 + qd * 2;
                const float2 pa = *(const float2*)&sO[ra * 66 + dcol];
                const float2 pb = *(const float2*)&sO[(ra + 8) * 66 + dcol];
                op[(((size_t)bh * N + orow) * DHD + dcol) >> 1] =
                    make_float2((o[mt][nb][0] + pa.x) * iA, (o[mt][nb][1] + pa.y) * iA);
                op[(((size_t)bh * N + orow + 8) * DHD + dcol) >> 1] =
                    make_float2((o[mt][nb][2] + pb.x) * iB, (o[mt][nb][3] + pb.y) * iB);
            }
        }
    }
}

// ---------------- launcher ----------------
extern "C" void kernel_launch(void* const* d_in, const int* in_sizes, int n_in,
                              void* d_out, int out_size)
{
    const float* Q   = (const float*)d_in[0];
    const float* K   = (const float*)d_in[1];
    const float* V   = (const float*)d_in[2];
    const int*   adj = (const int*)d_in[3];
    float*       out = (float*)d_out;

    const int N  = (int)(sqrt((double)in_sizes[3]) + 0.5);
    const int BH = in_sizes[0] / (N * DHD);

    const int adjB = (N * N / 32) / 256;
    const int cvtB = (BH * N * DHD / 4) / 256;
    prepass_kernel<<<adjB + cvtB, 256>>>((const int4*)adj, (const float4*)Q,
                                         (const float4*)K, (const float4*)V, N, adjB);

    cudaFuncSetAttribute(gat_hmma10_kernel,
                         cudaFuncAttributeMaxDynamicSharedMemorySize, SMEM_TOTAL);
    dim3 grid(N / BM, BH);
    gat_hmma10_kernel<<<grid, TPB, SMEM_TOTAL>>>(out, N);
}